// round 3
// baseline (speedup 1.0000x reference)
#include <cuda_runtime.h>
#include <cuda_bf16.h>
#include <math.h>

// Problem constants
#define S_LEN 2048
#define DIM   2048
#define NHEAD 16
#define QL    1536
#define KVL   512
#define NOPE  128
#define ROPE_D 64
#define VH    128
#define QKD   192   // NOPE + ROPE
#define EPS   1e-6f

// ---------------- scratch (device globals; no allocation allowed) ----------
__device__ float g_qdown[S_LEN * QL];
__device__ float g_qnorm[S_LEN * QL];
__device__ float g_kv   [S_LEN * (KVL + ROPE_D)];
__device__ float g_kvnorm[S_LEN * KVL];
__device__ float g_q    [S_LEN * NHEAD * QKD];     // roped in place
__device__ float g_kvu  [S_LEN * NHEAD * (NOPE + VH)];
__device__ float g_kpe  [S_LEN * ROPE_D];
__device__ float g_attn [S_LEN * NHEAD * VH];

// ---------------- GEMM: C[M,N] = A[M,K] * B[N,K]^T  (row-major) ------------
#define GBM 128
#define GBN 128
#define GBK 8

__global__ void __launch_bounds__(256) gemm_nt_kernel(
    const float* __restrict__ A, const float* __restrict__ B,
    float* __restrict__ C, int M, int N, int K)
{
    __shared__ float As[GBK][GBM + 4];
    __shared__ float Bs[GBK][GBN + 4];

    const int tid = threadIdx.x;
    const int tx = tid & 15;       // 0..15
    const int ty = tid >> 4;       // 0..15
    const int row0 = blockIdx.y * GBM;
    const int col0 = blockIdx.x * GBN;

    const int lr = tid >> 1;             // 0..127
    const int lc = (tid & 1) * 4;        // 0 or 4

    float acc[8][8];
#pragma unroll
    for (int i = 0; i < 8; i++)
#pragma unroll
        for (int j = 0; j < 8; j++) acc[i][j] = 0.f;

    for (int k0 = 0; k0 < K; k0 += GBK) {
        float4 av = make_float4(0.f, 0.f, 0.f, 0.f);
        if (row0 + lr < M)
            av = *(const float4*)(A + (size_t)(row0 + lr) * K + k0 + lc);
        As[lc + 0][lr] = av.x; As[lc + 1][lr] = av.y;
        As[lc + 2][lr] = av.z; As[lc + 3][lr] = av.w;

        float4 bv = make_float4(0.f, 0.f, 0.f, 0.f);
        if (col0 + lr < N)
            bv = *(const float4*)(B + (size_t)(col0 + lr) * K + k0 + lc);
        Bs[lc + 0][lr] = bv.x; Bs[lc + 1][lr] = bv.y;
        Bs[lc + 2][lr] = bv.z; Bs[lc + 3][lr] = bv.w;

        __syncthreads();

#pragma unroll
        for (int k = 0; k < GBK; ++k) {
            float a[8], b[8];
            *(float4*)(a)     = *(const float4*)&As[k][ty * 8];
            *(float4*)(a + 4) = *(const float4*)&As[k][ty * 8 + 4];
            *(float4*)(b)     = *(const float4*)&Bs[k][tx * 8];
            *(float4*)(b + 4) = *(const float4*)&Bs[k][tx * 8 + 4];
#pragma unroll
            for (int i = 0; i < 8; i++)
#pragma unroll
                for (int j = 0; j < 8; j++)
                    acc[i][j] += a[i] * b[j];
        }
        __syncthreads();
    }

#pragma unroll
    for (int i = 0; i < 8; i++) {
        int r = row0 + ty * 8 + i;
        if (r >= M) continue;
#pragma unroll
        for (int j = 0; j < 8; j++) {
            int c = col0 + tx * 8 + j;
            if (c < N) C[(size_t)r * N + c] = acc[i][j];
        }
    }
}

// ---------------- RMSNorm: out = x * rsqrt(mean(x^2)+eps) * w --------------
__global__ void rms_kernel(const float* __restrict__ in, const float* __restrict__ w,
                           float* __restrict__ out, int n, int istride, int ostride)
{
    const int row = blockIdx.x;
    const float* x = in + (size_t)row * istride;

    float ss = 0.f;
    for (int i = threadIdx.x; i < n; i += blockDim.x) {
        float v = x[i];
        ss += v * v;
    }
#pragma unroll
    for (int o = 16; o; o >>= 1) ss += __shfl_xor_sync(0xffffffffu, ss, o);

    __shared__ float warpsum[8];
    __shared__ float sScale;
    const int wid = threadIdx.x >> 5;
    if ((threadIdx.x & 31) == 0) warpsum[wid] = ss;
    __syncthreads();
    if (threadIdx.x == 0) {
        float tot = 0.f;
        for (int i = 0; i < (int)(blockDim.x >> 5); i++) tot += warpsum[i];
        sScale = rsqrtf(tot / (float)n + EPS);
    }
    __syncthreads();
    const float sc = sScale;
    for (int i = threadIdx.x; i < n; i += blockDim.x)
        out[(size_t)row * ostride + i] = x[i] * sc * w[i];
}

// ---------------- RoPE: q_pe (in place on g_q) and k_pe -> g_kpe -----------
__global__ void rope_kernel(float* __restrict__ q, const float* __restrict__ kv,
                            float* __restrict__ kpe)
{
    const int s = blockIdx.x;
    const int tid = threadIdx.x;        // 544 = 17 warps
    const int h = tid >> 5;             // 0..16
    const int i = tid & 31;             // freq index 0..31
    if (h > 16) return;

    const float invf = powf(10000.f, -(float)i / 32.f);
    const float ang = (float)s * invf;
    float sn, c;
    sincosf(ang, &sn, &c);

    if (h < 16) {
        float* p = q + (size_t)s * (NHEAD * QKD) + h * QKD + NOPE + 2 * i;
        const float x0 = p[0], x1 = p[1];
        p[0] = x0 * c - x1 * sn;
        p[1] = x0 * sn + x1 * c;
    } else {
        const float* p = kv + (size_t)s * (KVL + ROPE_D) + KVL + 2 * i;
        const float x0 = p[0], x1 = p[1];
        kpe[(size_t)s * ROPE_D + 2 * i]     = x0 * c - x1 * sn;
        kpe[(size_t)s * ROPE_D + 2 * i + 1] = x0 * sn + x1 * c;
    }
}

// ---------------- Flash attention (causal, online softmax) -----------------
// grid: (S_LEN/64, NHEAD), block: 256 threads
// smem layout (floats):
//   Qt[192][68], Kt[192][68], Vs[64][132], Pt[64][68], sAlpha[64], sL[64]
#define LDT 68
#define LDV 132
#define ATTN_SMEM_FLOATS (QKD*LDT*2 + 64*LDV + 64*LDT + 128)

__global__ void __launch_bounds__(256) attn_kernel(
    const float* __restrict__ q,     // [S, H*QKD] roped
    const float* __restrict__ kvu,   // [S, H*256] (k_nope | v)
    const float* __restrict__ kpe,   // [S, 64]
    float* __restrict__ out)         // [S, H*VH]
{
    const int qt = blockIdx.x;
    const int h  = blockIdx.y;
    extern __shared__ float sm[];
    float* Qt = sm;                          // [192][68] transposed
    float* Kt = Qt + QKD * LDT;              // [192][68] transposed
    float* Vs = Kt + QKD * LDT;              // [64][132] row-major
    float* Pt = Vs + 64 * LDV;               // [64][68]  Pt[t][i]
    float* sAlpha = Pt + 64 * LDT;           // [64]
    float* sL     = sAlpha + 64;             // [64]

    const int tid = threadIdx.x;
    const int tx = tid & 15;     // 0..15
    const int ty = tid >> 4;     // 0..15

    // load Q tile transposed: Qt[d][i]
    for (int e = tid; e < 64 * (QKD / 4); e += 256) {
        int i = e / (QKD / 4), c4 = (e % (QKD / 4)) * 4;
        float4 v = *(const float4*)(q + (size_t)(qt * 64 + i) * (NHEAD * QKD) + h * QKD + c4);
        Qt[(c4 + 0) * LDT + i] = v.x; Qt[(c4 + 1) * LDT + i] = v.y;
        Qt[(c4 + 2) * LDT + i] = v.z; Qt[(c4 + 3) * LDT + i] = v.w;
    }

    float accO[4][8];
#pragma unroll
    for (int i = 0; i < 4; i++)
#pragma unroll
        for (int j = 0; j < 8; j++) accO[i][j] = 0.f;

    float m_i = -INFINITY, l_i = 0.f;      // valid for tid < 64 (row = tid)
    const float scale = rsqrtf((float)QKD);

    for (int kt = 0; kt <= qt; ++kt) {
        __syncthreads();   // protect Kt/Vs (read in previous PV) before overwrite
        // load K tile transposed: dims 0..127 from kvu, 128..191 from kpe
        for (int e = tid; e < 64 * (QKD / 4); e += 256) {
            int t = e / (QKD / 4), c4 = (e % (QKD / 4)) * 4;
            int tg = kt * 64 + t;
            float4 v;
            if (c4 < NOPE)
                v = *(const float4*)(kvu + (size_t)tg * (NHEAD * 256) + h * 256 + c4);
            else
                v = *(const float4*)(kpe + (size_t)tg * ROPE_D + (c4 - NOPE));
            Kt[(c4 + 0) * LDT + t] = v.x; Kt[(c4 + 1) * LDT + t] = v.y;
            Kt[(c4 + 2) * LDT + t] = v.z; Kt[(c4 + 3) * LDT + t] = v.w;
        }
        // load V tile row-major
        for (int e = tid; e < 64 * (VH / 4); e += 256) {
            int t = e / (VH / 4), c4 = (e % (VH / 4)) * 4;
            int tg = kt * 64 + t;
            *(float4*)&Vs[t * LDV + c4] =
                *(const float4*)(kvu + (size_t)tg * (NHEAD * 256) + h * 256 + NOPE + c4);
        }
        __syncthreads();

        // S = Q K^T : thread computes rows i=4ty+ii, cols j=4tx+jj
        float s[4][4];
#pragma unroll
        for (int a = 0; a < 4; a++)
#pragma unroll
            for (int b = 0; b < 4; b++) s[a][b] = 0.f;

        for (int d = 0; d < QKD; ++d) {
            float a[4], b[4];
            *(float4*)a = *(const float4*)&Qt[d * LDT + 4 * ty];
            *(float4*)b = *(const float4*)&Kt[d * LDT + 4 * tx];
#pragma unroll
            for (int ii = 0; ii < 4; ii++)
#pragma unroll
                for (int jj = 0; jj < 4; jj++)
                    s[ii][jj] += a[ii] * b[jj];
        }
        // write transposed into Pt[j][i]
#pragma unroll
        for (int jj = 0; jj < 4; jj++)
            *(float4*)&Pt[(4 * tx + jj) * LDT + 4 * ty] =
                make_float4(s[0][jj], s[1][jj], s[2][jj], s[3][jj]);
        __syncthreads();

        // online softmax, one thread per row
        if (tid < 64) {
            const int i = tid;
            const int tlim = (kt == qt) ? (i + 1) : 64;
            float tmax = -INFINITY;
            for (int t = 0; t < tlim; t++)
                tmax = fmaxf(tmax, Pt[t * LDT + i]);
            tmax *= scale;
            const float mn = fmaxf(m_i, tmax);
            const float alpha = (m_i == -INFINITY) ? 0.f : expf(m_i - mn);
            float lsum = 0.f;
            for (int t = 0; t < 64; t++) {
                float p = (t < tlim) ? expf(Pt[t * LDT + i] * scale - mn) : 0.f;
                Pt[t * LDT + i] = p;
                lsum += p;
            }
            l_i = l_i * alpha + lsum;
            m_i = mn;
            sAlpha[i] = alpha;
        }
        __syncthreads();

        // O = alpha*O + P @ V : rows i=4ty+ii, cols c=8tx+cc
        {
            float al[4];
#pragma unroll
            for (int ii = 0; ii < 4; ii++) al[ii] = sAlpha[4 * ty + ii];
#pragma unroll
            for (int ii = 0; ii < 4; ii++)
#pragma unroll
                for (int cc = 0; cc < 8; cc++) accO[ii][cc] *= al[ii];

            for (int t = 0; t < 64; t++) {
                float a[4], b[8];
                *(float4*)a = *(const float4*)&Pt[t * LDT + 4 * ty];
                *(float4*)(b)     = *(const float4*)&Vs[t * LDV + 8 * tx];
                *(float4*)(b + 4) = *(const float4*)&Vs[t * LDV + 8 * tx + 4];
#pragma unroll
                for (int ii = 0; ii < 4; ii++)
#pragma unroll
                    for (int cc = 0; cc < 8; cc++)
                        accO[ii][cc] += a[ii] * b[cc];
            }
        }
    }

    if (tid < 64) sL[tid] = l_i;
    __syncthreads();

#pragma unroll
    for (int ii = 0; ii < 4; ii++) {
        const int i = 4 * ty + ii;
        const float inv_l = 1.f / sL[i];
        const int row = qt * 64 + i;
#pragma unroll
        for (int cc = 0; cc < 8; cc++)
            out[(size_t)row * (NHEAD * VH) + h * VH + 8 * tx + cc] = accO[ii][cc] * inv_l;
    }
}

// ---------------- host orchestration ---------------------------------------
static inline void launch_gemm_nt(const float* A, const float* B, float* C,
                                  int M, int N, int K)
{
    dim3 grid((N + GBN - 1) / GBN, (M + GBM - 1) / GBM);
    gemm_nt_kernel<<<grid, 256>>>(A, B, C, M, N, K);
}

extern "C" void kernel_launch(void* const* d_in, const int* in_sizes, int n_in,
                              void* d_out, int out_size)
{
    const float* x        = (const float*)d_in[0];   // [S, DIM]
    const float* wq_down  = (const float*)d_in[1];   // [QL, DIM]
    const float* q_norm_w = (const float*)d_in[2];   // [QL]
    const float* wq_up    = (const float*)d_in[3];   // [H*QKD, QL]
    const float* wkv_down = (const float*)d_in[4];   // [KVL+ROPE, DIM]
    const float* kv_norm_w= (const float*)d_in[5];   // [KVL]
    const float* wkv_up   = (const float*)d_in[6];   // [H*(NOPE+VH), KVL]
    const float* wo       = (const float*)d_in[7];   // [DIM, H*VH]
    float* out = (float*)d_out;

    float *qdown, *qnorm, *kv, *kvnorm, *qbuf, *kvu, *kpe, *attn;
    cudaGetSymbolAddress((void**)&qdown,  g_qdown);
    cudaGetSymbolAddress((void**)&qnorm,  g_qnorm);
    cudaGetSymbolAddress((void**)&kv,     g_kv);
    cudaGetSymbolAddress((void**)&kvnorm, g_kvnorm);
    cudaGetSymbolAddress((void**)&qbuf,   g_q);
    cudaGetSymbolAddress((void**)&kvu,    g_kvu);
    cudaGetSymbolAddress((void**)&kpe,    g_kpe);
    cudaGetSymbolAddress((void**)&attn,   g_attn);

    // 1) q_down = x @ wq_down^T, kv = x @ wkv_down^T
    launch_gemm_nt(x, wq_down, qdown, S_LEN, QL, DIM);
    launch_gemm_nt(x, wkv_down, kv, S_LEN, KVL + ROPE_D, DIM);

    // 2) RMSNorms
    rms_kernel<<<S_LEN, 256>>>(qdown, q_norm_w, qnorm, QL, QL, QL);
    rms_kernel<<<S_LEN, 256>>>(kv, kv_norm_w, kvnorm, KVL, KVL + ROPE_D, KVL);

    // 3) up-projections
    launch_gemm_nt(qnorm, wq_up, qbuf, S_LEN, NHEAD * QKD, QL);
    launch_gemm_nt(kvnorm, wkv_up, kvu, S_LEN, NHEAD * (NOPE + VH), KVL);

    // 4) rope (q in place, k_pe to g_kpe)
    rope_kernel<<<S_LEN, 544>>>(qbuf, kv, kpe);

    // 5) causal flash attention
    size_t attn_smem = (size_t)ATTN_SMEM_FLOATS * sizeof(float);
    cudaFuncSetAttribute(attn_kernel, cudaFuncAttributeMaxDynamicSharedMemorySize,
                         (int)attn_smem);
    dim3 agrid(S_LEN / 64, NHEAD);
    attn_kernel<<<agrid, 256, attn_smem>>>(qbuf, kvu, kpe, attn);

    // 6) output projection
    launch_gemm_nt(attn, wo, out, S_LEN, DIM, DIM);
}

// round 4
// speedup vs baseline: 1.3766x; 1.3766x over previous
#include <cuda_runtime.h>
#include <cuda_bf16.h>
#include <math.h>
#include <stdint.h>

// Problem constants
#define S_LEN 2048
#define DIM   2048
#define NHEAD 16
#define QL    1536
#define KVL   512
#define NOPE  128
#define ROPE_D 64
#define VH    128
#define QKD   192   // NOPE + ROPE
#define EPS   1e-6f

// ---------------- scratch (device globals; no allocation allowed) ----------
__device__ float g_qdown[S_LEN * QL];
__device__ float g_qnorm[S_LEN * QL];
__device__ float g_kv   [S_LEN * (KVL + ROPE_D)];
__device__ float g_kvnorm[S_LEN * KVL];
__device__ float g_q    [S_LEN * NHEAD * QKD];     // roped in place
__device__ float g_kvu  [S_LEN * NHEAD * (NOPE + VH)];
__device__ float g_kpe  [S_LEN * ROPE_D];
__device__ float g_attn [S_LEN * NHEAD * VH];

// bf16x3 operand scratch: A3 up to [2048, 3*2048], B3 up to [3072, 3*1536]
__device__ __nv_bfloat16 g_A3[(size_t)S_LEN * 3 * DIM];          // 12.58M elems
__device__ __nv_bfloat16 g_B3[(size_t)3072 * 3 * 1536];          // 14.16M elems

// ---------------- fp32 -> (hi,lo) bf16 split kernels -----------------------
// A mode: dst row layout [hi(K) | lo(K) | hi(K)]
// B mode: dst row layout [hi(K) | hi(K) | lo(K)]
__global__ void split3_kernel(const float* __restrict__ src,
                              __nv_bfloat16* __restrict__ dst,
                              int K, int modeB)
{
    const int r = blockIdx.y;
    const int k = blockIdx.x * 256 + threadIdx.x;
    if (k >= K) return;
    const float v = src[(size_t)r * K + k];
    const __nv_bfloat16 h = __float2bfloat16(v);
    const __nv_bfloat16 l = __float2bfloat16(v - __bfloat162float(h));
    __nv_bfloat16* d = dst + (size_t)r * 3 * K;
    d[k] = h;
    d[K + k]     = modeB ? h : l;
    d[2 * K + k] = modeB ? l : h;
}

// ---------------- bf16x3 tensor-core GEMM ----------------------------------
// C[M,N] = A3[M,K3] * B3[N,K3]^T  (bf16 operands, fp32 accumulate)
#define TBM 128
#define TBN 128
#define TBK 32
#define AP  40      // smem pitch in bf16 (80B = 5 x 16B units -> conflict-free ldmatrix)

__device__ __forceinline__ unsigned smem_u32(const void* p) {
    return (unsigned)__cvta_generic_to_shared(p);
}
__device__ __forceinline__ void cp16(unsigned s, const void* g, bool pred) {
    int sz = pred ? 16 : 0;
    asm volatile("cp.async.cg.shared.global [%0], [%1], 16, %2;\n"
                 :: "r"(s), "l"(g), "r"(sz));
}
__device__ __forceinline__ void ldsm_x4(uint32_t& r0, uint32_t& r1,
                                        uint32_t& r2, uint32_t& r3, unsigned addr) {
    asm volatile("ldmatrix.sync.aligned.m8n8.x4.shared.b16 {%0,%1,%2,%3}, [%4];"
                 : "=r"(r0), "=r"(r1), "=r"(r2), "=r"(r3) : "r"(addr));
}
__device__ __forceinline__ void mma16816(float* c, const uint32_t* a, const uint32_t* b) {
    asm volatile(
        "mma.sync.aligned.m16n8k16.row.col.f32.bf16.bf16.f32 "
        "{%0,%1,%2,%3}, {%4,%5,%6,%7}, {%8,%9}, {%0,%1,%2,%3};"
        : "+f"(c[0]), "+f"(c[1]), "+f"(c[2]), "+f"(c[3])
        : "r"(a[0]), "r"(a[1]), "r"(a[2]), "r"(a[3]), "r"(b[0]), "r"(b[1]));
}

__global__ void __launch_bounds__(256) gemm_bf16x3_kernel(
    const __nv_bfloat16* __restrict__ A,   // [M, K3]
    const __nv_bfloat16* __restrict__ B,   // [N, K3]
    float* __restrict__ C, int M, int N, int K3)
{
    __shared__ __nv_bfloat16 As[2][TBM * AP];
    __shared__ __nv_bfloat16 Bs[2][TBM * AP];

    const int tid = threadIdx.x, lane = tid & 31, wid = tid >> 5;
    const int wm = wid & 1;          // 0..1 : 64-row slab
    const int wn = wid >> 1;         // 0..3 : 32-col slab
    const int row0 = blockIdx.y * TBM, col0 = blockIdx.x * TBN;

    // gmem->smem mapping: thread owns 2 consecutive 16B chunks of one 32-col row
    const int c0 = tid * 2;
    const int lr = c0 >> 2;          // tile row (0..127)
    const int lu = c0 & 3;           // first 16B unit (0 or 2)
    const bool aval = (row0 + lr) < M;
    const bool bval = (col0 + lr) < N;
    const __nv_bfloat16* Ag = A + (size_t)(row0 + lr) * K3 + lu * 8;
    const __nv_bfloat16* Bg = B + (size_t)(col0 + lr) * K3 + lu * 8;
    const unsigned soff = (unsigned)((lr * AP + lu * 8) * 2);

    float acc[4][4][4];
#pragma unroll
    for (int i = 0; i < 4; i++)
#pragma unroll
        for (int j = 0; j < 4; j++)
#pragma unroll
            for (int k = 0; k < 4; k++) acc[i][j][k] = 0.f;

    const int NKB = K3 / TBK;

    // prologue: load kb=0 into buf 0
    {
        unsigned sa = smem_u32(As[0]) + soff;
        unsigned sb = smem_u32(Bs[0]) + soff;
        cp16(sa, Ag, aval);  cp16(sa + 16, Ag + 8, aval);
        cp16(sb, Bg, bval);  cp16(sb + 16, Bg + 8, bval);
        asm volatile("cp.async.commit_group;\n" ::: "memory");
    }

    for (int kb = 0; kb < NKB; ++kb) {
        const int cur = kb & 1;
        asm volatile("cp.async.wait_group 0;\n" ::: "memory");
        __syncthreads();

        if (kb + 1 < NKB) {
            const __nv_bfloat16* ga = Ag + (size_t)(kb + 1) * TBK;
            const __nv_bfloat16* gb = Bg + (size_t)(kb + 1) * TBK;
            unsigned sa = smem_u32(As[cur ^ 1]) + soff;
            unsigned sb = smem_u32(Bs[cur ^ 1]) + soff;
            cp16(sa, ga, aval);  cp16(sa + 16, ga + 8, aval);
            cp16(sb, gb, bval);  cp16(sb + 16, gb + 8, bval);
            asm volatile("cp.async.commit_group;\n" ::: "memory");
        }

        // compute on buffer `cur`
        const unsigned abase = smem_u32(As[cur]);
        const unsigned bbase = smem_u32(Bs[cur]);
        const unsigned aAddr = abase + (unsigned)(((wm * 64 + (lane & 15)) * AP
                                                  + (lane >> 4) * 8) * 2);
        const unsigned bAddr = bbase + (unsigned)(((wn * 32 + (lane >> 4) * 8 + (lane & 7)) * AP
                                                  + ((lane >> 3) & 1) * 8) * 2);
#pragma unroll
        for (int kk = 0; kk < 2; ++kk) {
            uint32_t af[4][4];
#pragma unroll
            for (int mt = 0; mt < 4; ++mt)
                ldsm_x4(af[mt][0], af[mt][1], af[mt][2], af[mt][3],
                        aAddr + (unsigned)((mt * 16 * AP + kk * 16) * 2));
            uint32_t bfr[4][2];
#pragma unroll
            for (int bp = 0; bp < 2; ++bp) {
                uint32_t r0, r1, r2, r3;
                ldsm_x4(r0, r1, r2, r3,
                        bAddr + (unsigned)((bp * 16 * AP + kk * 16) * 2));
                bfr[2 * bp][0] = r0;  bfr[2 * bp][1] = r1;
                bfr[2 * bp + 1][0] = r2;  bfr[2 * bp + 1][1] = r3;
            }
#pragma unroll
            for (int mt = 0; mt < 4; ++mt)
#pragma unroll
                for (int nt = 0; nt < 4; ++nt)
                    mma16816(acc[mt][nt], af[mt], bfr[nt]);
        }
        __syncthreads();
    }

    // epilogue
#pragma unroll
    for (int mt = 0; mt < 4; ++mt) {
#pragma unroll
        for (int nt = 0; nt < 4; ++nt) {
            const int r = row0 + wm * 64 + mt * 16 + (lane >> 2);
            const int c = col0 + wn * 32 + nt * 8 + (lane & 3) * 2;
            if (c < N) {
                if (r < M)
                    *(float2*)(C + (size_t)r * N + c) =
                        make_float2(acc[mt][nt][0], acc[mt][nt][1]);
                if (r + 8 < M)
                    *(float2*)(C + (size_t)(r + 8) * N + c) =
                        make_float2(acc[mt][nt][2], acc[mt][nt][3]);
            }
        }
    }
}

// ---------------- RMSNorm ---------------------------------------------------
__global__ void rms_kernel(const float* __restrict__ in, const float* __restrict__ w,
                           float* __restrict__ out, int n, int istride, int ostride)
{
    const int row = blockIdx.x;
    const float* x = in + (size_t)row * istride;

    float ss = 0.f;
    for (int i = threadIdx.x; i < n; i += blockDim.x) {
        float v = x[i];
        ss += v * v;
    }
#pragma unroll
    for (int o = 16; o; o >>= 1) ss += __shfl_xor_sync(0xffffffffu, ss, o);

    __shared__ float warpsum[8];
    __shared__ float sScale;
    const int wid = threadIdx.x >> 5;
    if ((threadIdx.x & 31) == 0) warpsum[wid] = ss;
    __syncthreads();
    if (threadIdx.x == 0) {
        float tot = 0.f;
        for (int i = 0; i < (int)(blockDim.x >> 5); i++) tot += warpsum[i];
        sScale = rsqrtf(tot / (float)n + EPS);
    }
    __syncthreads();
    const float sc = sScale;
    for (int i = threadIdx.x; i < n; i += blockDim.x)
        out[(size_t)row * ostride + i] = x[i] * sc * w[i];
}

// ---------------- RoPE ------------------------------------------------------
__global__ void rope_kernel(float* __restrict__ q, const float* __restrict__ kv,
                            float* __restrict__ kpe)
{
    const int s = blockIdx.x;
    const int tid = threadIdx.x;        // 544 = 17 warps
    const int h = tid >> 5;             // 0..16
    const int i = tid & 31;             // freq index 0..31
    if (h > 16) return;

    const float invf = powf(10000.f, -(float)i / 32.f);
    const float ang = (float)s * invf;
    float sn, c;
    sincosf(ang, &sn, &c);

    if (h < 16) {
        float* p = q + (size_t)s * (NHEAD * QKD) + h * QKD + NOPE + 2 * i;
        const float x0 = p[0], x1 = p[1];
        p[0] = x0 * c - x1 * sn;
        p[1] = x0 * sn + x1 * c;
    } else {
        const float* p = kv + (size_t)s * (KVL + ROPE_D) + KVL + 2 * i;
        const float x0 = p[0], x1 = p[1];
        kpe[(size_t)s * ROPE_D + 2 * i]     = x0 * c - x1 * sn;
        kpe[(size_t)s * ROPE_D + 2 * i + 1] = x0 * sn + x1 * c;
    }
}

// ---------------- Flash attention (causal, online softmax) -----------------
#define LDT 68
#define LDV 132
#define ATTN_SMEM_FLOATS (QKD*LDT*2 + 64*LDV + 64*LDT + 128)

__global__ void __launch_bounds__(256) attn_kernel(
    const float* __restrict__ q,     // [S, H*QKD] roped
    const float* __restrict__ kvu,   // [S, H*256] (k_nope | v)
    const float* __restrict__ kpe,   // [S, 64]
    float* __restrict__ out)         // [S, H*VH]
{
    const int qt = blockIdx.x;
    const int h  = blockIdx.y;
    extern __shared__ float sm[];
    float* Qt = sm;                          // [192][68] transposed
    float* Kt = Qt + QKD * LDT;              // [192][68] transposed
    float* Vs = Kt + QKD * LDT;              // [64][132] row-major
    float* Pt = Vs + 64 * LDV;               // [64][68]  Pt[t][i]
    float* sAlpha = Pt + 64 * LDT;           // [64]
    float* sL     = sAlpha + 64;             // [64]

    const int tid = threadIdx.x;
    const int tx = tid & 15;     // 0..15
    const int ty = tid >> 4;     // 0..15

    for (int e = tid; e < 64 * (QKD / 4); e += 256) {
        int i = e / (QKD / 4), c4 = (e % (QKD / 4)) * 4;
        float4 v = *(const float4*)(q + (size_t)(qt * 64 + i) * (NHEAD * QKD) + h * QKD + c4);
        Qt[(c4 + 0) * LDT + i] = v.x; Qt[(c4 + 1) * LDT + i] = v.y;
        Qt[(c4 + 2) * LDT + i] = v.z; Qt[(c4 + 3) * LDT + i] = v.w;
    }

    float accO[4][8];
#pragma unroll
    for (int i = 0; i < 4; i++)
#pragma unroll
        for (int j = 0; j < 8; j++) accO[i][j] = 0.f;

    float m_i = -INFINITY, l_i = 0.f;
    const float scale = rsqrtf((float)QKD);

    for (int kt = 0; kt <= qt; ++kt) {
        __syncthreads();
        for (int e = tid; e < 64 * (QKD / 4); e += 256) {
            int t = e / (QKD / 4), c4 = (e % (QKD / 4)) * 4;
            int tg = kt * 64 + t;
            float4 v;
            if (c4 < NOPE)
                v = *(const float4*)(kvu + (size_t)tg * (NHEAD * 256) + h * 256 + c4);
            else
                v = *(const float4*)(kpe + (size_t)tg * ROPE_D + (c4 - NOPE));
            Kt[(c4 + 0) * LDT + t] = v.x; Kt[(c4 + 1) * LDT + t] = v.y;
            Kt[(c4 + 2) * LDT + t] = v.z; Kt[(c4 + 3) * LDT + t] = v.w;
        }
        for (int e = tid; e < 64 * (VH / 4); e += 256) {
            int t = e / (VH / 4), c4 = (e % (VH / 4)) * 4;
            int tg = kt * 64 + t;
            *(float4*)&Vs[t * LDV + c4] =
                *(const float4*)(kvu + (size_t)tg * (NHEAD * 256) + h * 256 + NOPE + c4);
        }
        __syncthreads();

        float s[4][4];
#pragma unroll
        for (int a = 0; a < 4; a++)
#pragma unroll
            for (int b = 0; b < 4; b++) s[a][b] = 0.f;

        for (int d = 0; d < QKD; ++d) {
            float a[4], b[4];
            *(float4*)a = *(const float4*)&Qt[d * LDT + 4 * ty];
            *(float4*)b = *(const float4*)&Kt[d * LDT + 4 * tx];
#pragma unroll
            for (int ii = 0; ii < 4; ii++)
#pragma unroll
                for (int jj = 0; jj < 4; jj++)
                    s[ii][jj] += a[ii] * b[jj];
        }
#pragma unroll
        for (int jj = 0; jj < 4; jj++)
            *(float4*)&Pt[(4 * tx + jj) * LDT + 4 * ty] =
                make_float4(s[0][jj], s[1][jj], s[2][jj], s[3][jj]);
        __syncthreads();

        if (tid < 64) {
            const int i = tid;
            const int tlim = (kt == qt) ? (i + 1) : 64;
            float tmax = -INFINITY;
            for (int t = 0; t < tlim; t++)
                tmax = fmaxf(tmax, Pt[t * LDT + i]);
            tmax *= scale;
            const float mn = fmaxf(m_i, tmax);
            const float alpha = (m_i == -INFINITY) ? 0.f : expf(m_i - mn);
            float lsum = 0.f;
            for (int t = 0; t < 64; t++) {
                float p = (t < tlim) ? expf(Pt[t * LDT + i] * scale - mn) : 0.f;
                Pt[t * LDT + i] = p;
                lsum += p;
            }
            l_i = l_i * alpha + lsum;
            m_i = mn;
            sAlpha[i] = alpha;
        }
        __syncthreads();

        {
            float al[4];
#pragma unroll
            for (int ii = 0; ii < 4; ii++) al[ii] = sAlpha[4 * ty + ii];
#pragma unroll
            for (int ii = 0; ii < 4; ii++)
#pragma unroll
                for (int cc = 0; cc < 8; cc++) accO[ii][cc] *= al[ii];

            for (int t = 0; t < 64; t++) {
                float a[4], b[8];
                *(float4*)a = *(const float4*)&Pt[t * LDT + 4 * ty];
                *(float4*)(b)     = *(const float4*)&Vs[t * LDV + 8 * tx];
                *(float4*)(b + 4) = *(const float4*)&Vs[t * LDV + 8 * tx + 4];
#pragma unroll
                for (int ii = 0; ii < 4; ii++)
#pragma unroll
                    for (int cc = 0; cc < 8; cc++)
                        accO[ii][cc] += a[ii] * b[cc];
            }
        }
    }

    if (tid < 64) sL[tid] = l_i;
    __syncthreads();

#pragma unroll
    for (int ii = 0; ii < 4; ii++) {
        const int i = 4 * ty + ii;
        const float inv_l = 1.f / sL[i];
        const int row = qt * 64 + i;
#pragma unroll
        for (int cc = 0; cc < 8; cc++)
            out[(size_t)row * (NHEAD * VH) + h * VH + 8 * tx + cc] = accO[ii][cc] * inv_l;
    }
}

// ---------------- host orchestration ---------------------------------------
static inline void launch_split(const float* src, __nv_bfloat16* dst,
                                int rows, int K, int modeB)
{
    dim3 grid((K + 255) / 256, rows);
    split3_kernel<<<grid, 256>>>(src, dst, K, modeB);
}

static inline void launch_gemm3(const __nv_bfloat16* A3, const __nv_bfloat16* B3,
                                float* C, int M, int N, int K)
{
    dim3 grid((N + TBN - 1) / TBN, (M + TBM - 1) / TBM);
    gemm_bf16x3_kernel<<<grid, 256>>>(A3, B3, C, M, N, 3 * K);
}

extern "C" void kernel_launch(void* const* d_in, const int* in_sizes, int n_in,
                              void* d_out, int out_size)
{
    const float* x        = (const float*)d_in[0];   // [S, DIM]
    const float* wq_down  = (const float*)d_in[1];   // [QL, DIM]
    const float* q_norm_w = (const float*)d_in[2];   // [QL]
    const float* wq_up    = (const float*)d_in[3];   // [H*QKD, QL]
    const float* wkv_down = (const float*)d_in[4];   // [KVL+ROPE, DIM]
    const float* kv_norm_w= (const float*)d_in[5];   // [KVL]
    const float* wkv_up   = (const float*)d_in[6];   // [H*(NOPE+VH), KVL]
    const float* wo       = (const float*)d_in[7];   // [DIM, H*VH]
    float* out = (float*)d_out;

    float *qdown, *qnorm, *kv, *kvnorm, *qbuf, *kvu, *kpe, *attn;
    __nv_bfloat16 *A3, *B3;
    cudaGetSymbolAddress((void**)&qdown,  g_qdown);
    cudaGetSymbolAddress((void**)&qnorm,  g_qnorm);
    cudaGetSymbolAddress((void**)&kv,     g_kv);
    cudaGetSymbolAddress((void**)&kvnorm, g_kvnorm);
    cudaGetSymbolAddress((void**)&qbuf,   g_q);
    cudaGetSymbolAddress((void**)&kvu,    g_kvu);
    cudaGetSymbolAddress((void**)&kpe,    g_kpe);
    cudaGetSymbolAddress((void**)&attn,   g_attn);
    cudaGetSymbolAddress((void**)&A3,     g_A3);
    cudaGetSymbolAddress((void**)&B3,     g_B3);

    // 1) down-projections: q_down = x @ wq_down^T, kv = x @ wkv_down^T
    launch_split(x, A3, S_LEN, DIM, 0);                 // x reused for both
    launch_split(wq_down, B3, QL, DIM, 1);
    launch_gemm3(A3, B3, qdown, S_LEN, QL, DIM);
    launch_split(wkv_down, B3, KVL + ROPE_D, DIM, 1);
    launch_gemm3(A3, B3, kv, S_LEN, KVL + ROPE_D, DIM);

    // 2) RMSNorms
    rms_kernel<<<S_LEN, 256>>>(qdown, q_norm_w, qnorm, QL, QL, QL);
    rms_kernel<<<S_LEN, 256>>>(kv, kv_norm_w, kvnorm, KVL, KVL + ROPE_D, KVL);

    // 3) up-projections
    launch_split(qnorm, A3, S_LEN, QL, 0);
    launch_split(wq_up, B3, NHEAD * QKD, QL, 1);
    launch_gemm3(A3, B3, qbuf, S_LEN, NHEAD * QKD, QL);
    launch_split(kvnorm, A3, S_LEN, KVL, 0);
    launch_split(wkv_up, B3, NHEAD * (NOPE + VH), KVL, 1);
    launch_gemm3(A3, B3, kvu, S_LEN, NHEAD * (NOPE + VH), KVL);

    // 4) rope (q in place, k_pe to g_kpe)
    rope_kernel<<<S_LEN, 544>>>(qbuf, kv, kpe);

    // 5) causal flash attention
    size_t attn_smem = (size_t)ATTN_SMEM_FLOATS * sizeof(float);
    cudaFuncSetAttribute(attn_kernel, cudaFuncAttributeMaxDynamicSharedMemorySize,
                         (int)attn_smem);
    dim3 agrid(S_LEN / 64, NHEAD);
    attn_kernel<<<agrid, 256, attn_smem>>>(qbuf, kvu, kpe, attn);

    // 6) output projection
    launch_split(attn, A3, S_LEN, NHEAD * VH, 0);
    launch_split(wo, B3, DIM, NHEAD * VH, 1);
    launch_gemm3(A3, B3, out, S_LEN, DIM, NHEAD * VH);
}

// round 5
// speedup vs baseline: 1.4344x; 1.0420x over previous
#include <cuda_runtime.h>
#include <cuda_bf16.h>
#include <math.h>
#include <stdint.h>

// Problem constants
#define S_LEN 2048
#define DIM   2048
#define NHEAD 16
#define QL    1536
#define KVL   512
#define NOPE  128
#define ROPE_D 64
#define VH    128
#define QKD   192   // NOPE + ROPE
#define EPS   1e-6f

// ---------------- scratch (device globals; no allocation allowed) ----------
__device__ float g_qdown[S_LEN * QL];
__device__ float g_kv   [S_LEN * (KVL + ROPE_D)];
__device__ float g_kvnorm[S_LEN * KVL];
__device__ float g_q    [S_LEN * NHEAD * QKD];     // roped in place
__device__ float g_kvu  [S_LEN * NHEAD * (NOPE + VH)];
__device__ float g_kpe  [S_LEN * ROPE_D];

// bf16x3 operand scratch
__device__ __nv_bfloat16 g_A3[(size_t)S_LEN * 3 * DIM];          // 12.58M elems
__device__ __nv_bfloat16 g_B3[(size_t)3072 * 3 * 1536];          // 14.16M elems

// ---------------- fp32 -> (hi,lo) bf16 split kernels -----------------------
// A mode: dst row layout [hi(K) | lo(K) | hi(K)]
// B mode: dst row layout [hi(K) | hi(K) | lo(K)]
__global__ void split3_kernel(const float* __restrict__ src,
                              __nv_bfloat16* __restrict__ dst,
                              int K, int modeB)
{
    const int r = blockIdx.y;
    const int k = blockIdx.x * 256 + threadIdx.x;
    if (k >= K) return;
    const float v = src[(size_t)r * K + k];
    const __nv_bfloat16 h = __float2bfloat16(v);
    const __nv_bfloat16 l = __float2bfloat16(v - __bfloat162float(h));
    __nv_bfloat16* d = dst + (size_t)r * 3 * K;
    d[k] = h;
    d[K + k]     = modeB ? h : l;
    d[2 * K + k] = modeB ? l : h;
}

// ---------------- RMSNorm (fp32 out) ---------------------------------------
__global__ void rms_kernel(const float* __restrict__ in, const float* __restrict__ w,
                           float* __restrict__ out, int n, int istride, int ostride)
{
    const int row = blockIdx.x;
    const float* x = in + (size_t)row * istride;

    float ss = 0.f;
    for (int i = threadIdx.x; i < n; i += blockDim.x) {
        float v = x[i];
        ss += v * v;
    }
#pragma unroll
    for (int o = 16; o; o >>= 1) ss += __shfl_xor_sync(0xffffffffu, ss, o);

    __shared__ float warpsum[8];
    __shared__ float sScale;
    const int wid = threadIdx.x >> 5;
    if ((threadIdx.x & 31) == 0) warpsum[wid] = ss;
    __syncthreads();
    if (threadIdx.x == 0) {
        float tot = 0.f;
        for (int i = 0; i < (int)(blockDim.x >> 5); i++) tot += warpsum[i];
        sScale = rsqrtf(tot / (float)n + EPS);
    }
    __syncthreads();
    const float sc = sScale;
    for (int i = threadIdx.x; i < n; i += blockDim.x)
        out[(size_t)row * ostride + i] = x[i] * sc * w[i];
}

// ---------------- RMSNorm fused with bf16x3 A-split ------------------------
__global__ void rms_split_kernel(const float* __restrict__ in, const float* __restrict__ w,
                                 __nv_bfloat16* __restrict__ dst, int n)
{
    const int row = blockIdx.x;
    const float* x = in + (size_t)row * n;

    float ss = 0.f;
    for (int i = threadIdx.x; i < n; i += blockDim.x) {
        float v = x[i];
        ss += v * v;
    }
#pragma unroll
    for (int o = 16; o; o >>= 1) ss += __shfl_xor_sync(0xffffffffu, ss, o);

    __shared__ float warpsum[8];
    __shared__ float sScale;
    const int wid = threadIdx.x >> 5;
    if ((threadIdx.x & 31) == 0) warpsum[wid] = ss;
    __syncthreads();
    if (threadIdx.x == 0) {
        float tot = 0.f;
        for (int i = 0; i < (int)(blockDim.x >> 5); i++) tot += warpsum[i];
        sScale = rsqrtf(tot / (float)n + EPS);
    }
    __syncthreads();
    const float sc = sScale;
    __nv_bfloat16* d = dst + (size_t)row * 3 * n;
    for (int i = threadIdx.x; i < n; i += blockDim.x) {
        const float v = x[i] * sc * w[i];
        const __nv_bfloat16 h = __float2bfloat16(v);
        const __nv_bfloat16 l = __float2bfloat16(v - __bfloat162float(h));
        d[i] = h; d[n + i] = l; d[2 * n + i] = h;
    }
}

// ---------------- bf16x3 tensor-core GEMM (v3: 4-stage pipeline) -----------
// C[M,N] = A3[M,K3] * B3[N,K3]^T  (bf16 operands, fp32 accumulate)
#define TBM 128
#define TBN 128
#define TBK 32
#define AP  40      // smem pitch in bf16 (80B = 5 x 16B units -> conflict-free)
#define STAGES 4
#define GEMM_SMEM (STAGES * 2 * TBM * AP * 2)   // bytes = 81920

__device__ __forceinline__ unsigned smem_u32(const void* p) {
    return (unsigned)__cvta_generic_to_shared(p);
}
__device__ __forceinline__ void cp16(unsigned s, const void* g, bool pred) {
    int sz = pred ? 16 : 0;
    asm volatile("cp.async.cg.shared.global [%0], [%1], 16, %2;\n"
                 :: "r"(s), "l"(g), "r"(sz));
}
__device__ __forceinline__ void ldsm_x4(uint32_t& r0, uint32_t& r1,
                                        uint32_t& r2, uint32_t& r3, unsigned addr) {
    asm volatile("ldmatrix.sync.aligned.m8n8.x4.shared.b16 {%0,%1,%2,%3}, [%4];"
                 : "=r"(r0), "=r"(r1), "=r"(r2), "=r"(r3) : "r"(addr));
}
__device__ __forceinline__ void mma16816(float* c, const uint32_t* a, const uint32_t* b) {
    asm volatile(
        "mma.sync.aligned.m16n8k16.row.col.f32.bf16.bf16.f32 "
        "{%0,%1,%2,%3}, {%4,%5,%6,%7}, {%8,%9}, {%0,%1,%2,%3};"
        : "+f"(c[0]), "+f"(c[1]), "+f"(c[2]), "+f"(c[3])
        : "r"(a[0]), "r"(a[1]), "r"(a[2]), "r"(a[3]), "r"(b[0]), "r"(b[1]));
}

__global__ void __launch_bounds__(256) gemm_bf16x3_kernel(
    const __nv_bfloat16* __restrict__ A,   // [M, K3]
    const __nv_bfloat16* __restrict__ B,   // [N, K3]
    float* __restrict__ C, int M, int N, int K3)
{
    extern __shared__ __nv_bfloat16 smem[];
    __nv_bfloat16* As = smem;                       // [STAGES][TBM*AP]
    __nv_bfloat16* Bs = smem + STAGES * TBM * AP;   // [STAGES][TBM*AP]

    const int tid = threadIdx.x, lane = tid & 31, wid = tid >> 5;
    const int wm = wid & 1;          // 0..1 : 64-row slab
    const int wn = wid >> 1;         // 0..3 : 32-col slab
    const int row0 = blockIdx.y * TBM, col0 = blockIdx.x * TBN;

    // gmem->smem mapping: thread owns 2 consecutive 16B chunks of one 32-col row
    const int c0 = tid * 2;
    const int lr = c0 >> 2;          // tile row (0..127)
    const int lu = c0 & 3;           // first 16B unit (0 or 2)
    const bool aval = (row0 + lr) < M;
    const bool bval = (col0 + lr) < N;
    const __nv_bfloat16* Ag = A + (size_t)(row0 + lr) * K3 + lu * 8;
    const __nv_bfloat16* Bg = B + (size_t)(col0 + lr) * K3 + lu * 8;
    const unsigned soff = (unsigned)((lr * AP + lu * 8) * 2);

    float acc[4][4][4];
#pragma unroll
    for (int i = 0; i < 4; i++)
#pragma unroll
        for (int j = 0; j < 4; j++)
#pragma unroll
            for (int k = 0; k < 4; k++) acc[i][j][k] = 0.f;

    const int NKB = K3 / TBK;

#define ISSUE_STAGE(KB, ST) do {                                              \
        unsigned sa = smem_u32(As + (ST) * TBM * AP) + soff;                  \
        unsigned sb = smem_u32(Bs + (ST) * TBM * AP) + soff;                  \
        const __nv_bfloat16* ga = Ag + (size_t)(KB) * TBK;                    \
        const __nv_bfloat16* gb = Bg + (size_t)(KB) * TBK;                    \
        cp16(sa, ga, aval);  cp16(sa + 16, ga + 8, aval);                     \
        cp16(sb, gb, bval);  cp16(sb + 16, gb + 8, bval);                     \
        asm volatile("cp.async.commit_group;\n" ::: "memory");                \
    } while (0)

    // prologue: 3 groups in flight
    ISSUE_STAGE(0, 0);
    ISSUE_STAGE(1, 1);
    ISSUE_STAGE(2, 2);

    const unsigned aoff = (unsigned)(((wm * 64 + (lane & 15)) * AP + (lane >> 4) * 8) * 2);
    const unsigned boff = (unsigned)(((wn * 32 + (lane >> 4) * 8 + (lane & 7)) * AP
                                      + ((lane >> 3) & 1) * 8) * 2);

    for (int kb = 0; kb < NKB; ++kb) {
        asm volatile("cp.async.wait_group 2;\n" ::: "memory");
        __syncthreads();

        if (kb + 3 < NKB) { ISSUE_STAGE(kb + 3, (kb + 3) & 3); }
        else { asm volatile("cp.async.commit_group;\n" ::: "memory"); }

        const int st = kb & 3;
        const unsigned aAddr = smem_u32(As + st * TBM * AP) + aoff;
        const unsigned bAddr = smem_u32(Bs + st * TBM * AP) + boff;

        // batch-load ALL fragments of this K-chunk (both kk halves)
        uint32_t af[2][4][4];
        uint32_t bfr[2][4][2];
#pragma unroll
        for (int kk = 0; kk < 2; ++kk) {
#pragma unroll
            for (int mt = 0; mt < 4; ++mt)
                ldsm_x4(af[kk][mt][0], af[kk][mt][1], af[kk][mt][2], af[kk][mt][3],
                        aAddr + (unsigned)((mt * 16 * AP + kk * 16) * 2));
#pragma unroll
            for (int bp = 0; bp < 2; ++bp) {
                uint32_t r0, r1, r2, r3;
                ldsm_x4(r0, r1, r2, r3,
                        bAddr + (unsigned)((bp * 16 * AP + kk * 16) * 2));
                bfr[kk][2 * bp][0] = r0;      bfr[kk][2 * bp][1] = r1;
                bfr[kk][2 * bp + 1][0] = r2;  bfr[kk][2 * bp + 1][1] = r3;
            }
        }
#pragma unroll
        for (int kk = 0; kk < 2; ++kk)
#pragma unroll
            for (int mt = 0; mt < 4; ++mt)
#pragma unroll
                for (int nt = 0; nt < 4; ++nt)
                    mma16816(acc[mt][nt], af[kk][mt], bfr[kk][nt]);
    }

    // epilogue
#pragma unroll
    for (int mt = 0; mt < 4; ++mt) {
#pragma unroll
        for (int nt = 0; nt < 4; ++nt) {
            const int r = row0 + wm * 64 + mt * 16 + (lane >> 2);
            const int c = col0 + wn * 32 + nt * 8 + (lane & 3) * 2;
            if (c < N) {
                if (r < M)
                    *(float2*)(C + (size_t)r * N + c) =
                        make_float2(acc[mt][nt][0], acc[mt][nt][1]);
                if (r + 8 < M)
                    *(float2*)(C + (size_t)(r + 8) * N + c) =
                        make_float2(acc[mt][nt][2], acc[mt][nt][3]);
            }
        }
    }
#undef ISSUE_STAGE
}

// ---------------- RoPE ------------------------------------------------------
__global__ void rope_kernel(float* __restrict__ q, const float* __restrict__ kv,
                            float* __restrict__ kpe)
{
    const int s = blockIdx.x;
    const int tid = threadIdx.x;        // 544 = 17 warps
    const int h = tid >> 5;             // 0..16
    const int i = tid & 31;             // freq index 0..31
    if (h > 16) return;

    const float invf = powf(10000.f, -(float)i / 32.f);
    const float ang = (float)s * invf;
    float sn, c;
    sincosf(ang, &sn, &c);

    if (h < 16) {
        float* p = q + (size_t)s * (NHEAD * QKD) + h * QKD + NOPE + 2 * i;
        const float x0 = p[0], x1 = p[1];
        p[0] = x0 * c - x1 * sn;
        p[1] = x0 * sn + x1 * c;
    } else {
        const float* p = kv + (size_t)s * (KVL + ROPE_D) + KVL + 2 * i;
        const float x0 = p[0], x1 = p[1];
        kpe[(size_t)s * ROPE_D + 2 * i]     = x0 * c - x1 * sn;
        kpe[(size_t)s * ROPE_D + 2 * i + 1] = x0 * sn + x1 * c;
    }
}

// ---------------- Flash attention (causal; epilogue fused bf16x3 split) ----
#define LDT 68
#define LDV 132
#define ATTN_SMEM_FLOATS (QKD*LDT*2 + 64*LDV + 64*LDT + 128)
#define AK (NHEAD * VH)    // 2048 = K of the wo GEMM

__global__ void __launch_bounds__(256) attn_kernel(
    const float* __restrict__ q,     // [S, H*QKD] roped
    const float* __restrict__ kvu,   // [S, H*256] (k_nope | v)
    const float* __restrict__ kpe,   // [S, 64]
    __nv_bfloat16* __restrict__ outA3)  // [S, 3*2048] bf16x3 A-layout
{
    const int qt = blockIdx.x;
    const int h  = blockIdx.y;
    extern __shared__ float sm[];
    float* Qt = sm;                          // [192][68] transposed
    float* Kt = Qt + QKD * LDT;              // [192][68] transposed
    float* Vs = Kt + QKD * LDT;              // [64][132] row-major
    float* Pt = Vs + 64 * LDV;               // [64][68]  Pt[t][i]
    float* sAlpha = Pt + 64 * LDT;           // [64]
    float* sL     = sAlpha + 64;             // [64]

    const int tid = threadIdx.x;
    const int tx = tid & 15;     // 0..15
    const int ty = tid >> 4;     // 0..15

    for (int e = tid; e < 64 * (QKD / 4); e += 256) {
        int i = e / (QKD / 4), c4 = (e % (QKD / 4)) * 4;
        float4 v = *(const float4*)(q + (size_t)(qt * 64 + i) * (NHEAD * QKD) + h * QKD + c4);
        Qt[(c4 + 0) * LDT + i] = v.x; Qt[(c4 + 1) * LDT + i] = v.y;
        Qt[(c4 + 2) * LDT + i] = v.z; Qt[(c4 + 3) * LDT + i] = v.w;
    }

    float accO[4][8];
#pragma unroll
    for (int i = 0; i < 4; i++)
#pragma unroll
        for (int j = 0; j < 8; j++) accO[i][j] = 0.f;

    float m_i = -INFINITY, l_i = 0.f;
    const float scale = rsqrtf((float)QKD);

    for (int kt = 0; kt <= qt; ++kt) {
        __syncthreads();
        for (int e = tid; e < 64 * (QKD / 4); e += 256) {
            int t = e / (QKD / 4), c4 = (e % (QKD / 4)) * 4;
            int tg = kt * 64 + t;
            float4 v;
            if (c4 < NOPE)
                v = *(const float4*)(kvu + (size_t)tg * (NHEAD * 256) + h * 256 + c4);
            else
                v = *(const float4*)(kpe + (size_t)tg * ROPE_D + (c4 - NOPE));
            Kt[(c4 + 0) * LDT + t] = v.x; Kt[(c4 + 1) * LDT + t] = v.y;
            Kt[(c4 + 2) * LDT + t] = v.z; Kt[(c4 + 3) * LDT + t] = v.w;
        }
        for (int e = tid; e < 64 * (VH / 4); e += 256) {
            int t = e / (VH / 4), c4 = (e % (VH / 4)) * 4;
            int tg = kt * 64 + t;
            *(float4*)&Vs[t * LDV + c4] =
                *(const float4*)(kvu + (size_t)tg * (NHEAD * 256) + h * 256 + NOPE + c4);
        }
        __syncthreads();

        float s[4][4];
#pragma unroll
        for (int a = 0; a < 4; a++)
#pragma unroll
            for (int b = 0; b < 4; b++) s[a][b] = 0.f;

        for (int d = 0; d < QKD; ++d) {
            float a[4], b[4];
            *(float4*)a = *(const float4*)&Qt[d * LDT + 4 * ty];
            *(float4*)b = *(const float4*)&Kt[d * LDT + 4 * tx];
#pragma unroll
            for (int ii = 0; ii < 4; ii++)
#pragma unroll
                for (int jj = 0; jj < 4; jj++)
                    s[ii][jj] += a[ii] * b[jj];
        }
#pragma unroll
        for (int jj = 0; jj < 4; jj++)
            *(float4*)&Pt[(4 * tx + jj) * LDT + 4 * ty] =
                make_float4(s[0][jj], s[1][jj], s[2][jj], s[3][jj]);
        __syncthreads();

        if (tid < 64) {
            const int i = tid;
            const int tlim = (kt == qt) ? (i + 1) : 64;
            float tmax = -INFINITY;
            for (int t = 0; t < tlim; t++)
                tmax = fmaxf(tmax, Pt[t * LDT + i]);
            tmax *= scale;
            const float mn = fmaxf(m_i, tmax);
            const float alpha = (m_i == -INFINITY) ? 0.f : expf(m_i - mn);
            float lsum = 0.f;
            for (int t = 0; t < 64; t++) {
                float p = (t < tlim) ? expf(Pt[t * LDT + i] * scale - mn) : 0.f;
                Pt[t * LDT + i] = p;
                lsum += p;
            }
            l_i = l_i * alpha + lsum;
            m_i = mn;
            sAlpha[i] = alpha;
        }
        __syncthreads();

        {
            float al[4];
#pragma unroll
            for (int ii = 0; ii < 4; ii++) al[ii] = sAlpha[4 * ty + ii];
#pragma unroll
            for (int ii = 0; ii < 4; ii++)
#pragma unroll
                for (int cc = 0; cc < 8; cc++) accO[ii][cc] *= al[ii];

            for (int t = 0; t < 64; t++) {
                float a[4], b[8];
                *(float4*)a = *(const float4*)&Pt[t * LDT + 4 * ty];
                *(float4*)(b)     = *(const float4*)&Vs[t * LDV + 8 * tx];
                *(float4*)(b + 4) = *(const float4*)&Vs[t * LDV + 8 * tx + 4];
#pragma unroll
                for (int ii = 0; ii < 4; ii++)
#pragma unroll
                    for (int cc = 0; cc < 8; cc++)
                        accO[ii][cc] += a[ii] * b[cc];
            }
        }
    }

    if (tid < 64) sL[tid] = l_i;
    __syncthreads();

    // fused epilogue: write bf16x3 A-operand layout [hi | lo | hi], K = 2048
#pragma unroll
    for (int ii = 0; ii < 4; ii++) {
        const int i = 4 * ty + ii;
        const float inv_l = 1.f / sL[i];
        const int row = qt * 64 + i;
        __nv_bfloat16* d = outA3 + (size_t)row * 3 * AK;
#pragma unroll
        for (int cc = 0; cc < 8; cc++) {
            const float v = accO[ii][cc] * inv_l;
            const int col = h * VH + 8 * tx + cc;
            const __nv_bfloat16 hv = __float2bfloat16(v);
            const __nv_bfloat16 lv = __float2bfloat16(v - __bfloat162float(hv));
            d[col] = hv; d[AK + col] = lv; d[2 * AK + col] = hv;
        }
    }
}

// ---------------- host orchestration ---------------------------------------
static inline void launch_split(const float* src, __nv_bfloat16* dst,
                                int rows, int K, int modeB)
{
    dim3 grid((K + 255) / 256, rows);
    split3_kernel<<<grid, 256>>>(src, dst, K, modeB);
}

static inline void launch_gemm3(const __nv_bfloat16* A3, const __nv_bfloat16* B3,
                                float* C, int M, int N, int K)
{
    cudaFuncSetAttribute(gemm_bf16x3_kernel,
                         cudaFuncAttributeMaxDynamicSharedMemorySize, GEMM_SMEM);
    dim3 grid((N + TBN - 1) / TBN, (M + TBM - 1) / TBM);
    gemm_bf16x3_kernel<<<grid, 256, GEMM_SMEM>>>(A3, B3, C, M, N, 3 * K);
}

extern "C" void kernel_launch(void* const* d_in, const int* in_sizes, int n_in,
                              void* d_out, int out_size)
{
    const float* x        = (const float*)d_in[0];   // [S, DIM]
    const float* wq_down  = (const float*)d_in[1];   // [QL, DIM]
    const float* q_norm_w = (const float*)d_in[2];   // [QL]
    const float* wq_up    = (const float*)d_in[3];   // [H*QKD, QL]
    const float* wkv_down = (const float*)d_in[4];   // [KVL+ROPE, DIM]
    const float* kv_norm_w= (const float*)d_in[5];   // [KVL]
    const float* wkv_up   = (const float*)d_in[6];   // [H*(NOPE+VH), KVL]
    const float* wo       = (const float*)d_in[7];   // [DIM, H*VH]
    float* out = (float*)d_out;

    float *qdown, *kv, *kvnorm, *qbuf, *kvu, *kpe;
    __nv_bfloat16 *A3, *B3;
    cudaGetSymbolAddress((void**)&qdown,  g_qdown);
    cudaGetSymbolAddress((void**)&kv,     g_kv);
    cudaGetSymbolAddress((void**)&kvnorm, g_kvnorm);
    cudaGetSymbolAddress((void**)&qbuf,   g_q);
    cudaGetSymbolAddress((void**)&kvu,    g_kvu);
    cudaGetSymbolAddress((void**)&kpe,    g_kpe);
    cudaGetSymbolAddress((void**)&A3,     g_A3);
    cudaGetSymbolAddress((void**)&B3,     g_B3);

    // B3 second region for wkv_down (fits: 9.44M + 3.54M < 14.16M elems)
    __nv_bfloat16* B3b = B3 + (size_t)QL * 3 * DIM;

    // 1) splits for down-projections
    launch_split(x, A3, S_LEN, DIM, 0);                       // launch 1
    launch_split(wq_down, B3, QL, DIM, 1);                    // launch 2
    launch_split(wkv_down, B3b, KVL + ROPE_D, DIM, 1);        // launch 3

    // 2) down-projections (kv first so the BIG qdown GEMM lands at ncu slot)
    launch_gemm3(A3, B3b, kv, S_LEN, KVL + ROPE_D, DIM);      // launch 4
    rms_kernel<<<S_LEN, 256>>>(kv, kv_norm_w, kvnorm, KVL, KVL + ROPE_D, KVL); // 5
    launch_gemm3(A3, B3, qdown, S_LEN, QL, DIM);              // launch 6 (profiled)

    // 3) q up-projection (rms fused with split)
    rms_split_kernel<<<S_LEN, 256>>>(qdown, q_norm_w, A3, QL);
    launch_split(wq_up, B3, NHEAD * QKD, QL, 1);
    launch_gemm3(A3, B3, qbuf, S_LEN, NHEAD * QKD, QL);

    // 4) kv up-projection
    launch_split(kvnorm, A3, S_LEN, KVL, 0);
    launch_split(wkv_up, B3, NHEAD * (NOPE + VH), KVL, 1);
    launch_gemm3(A3, B3, kvu, S_LEN, NHEAD * (NOPE + VH), KVL);

    // 5) rope (q in place, k_pe to g_kpe)
    rope_kernel<<<S_LEN, 544>>>(qbuf, kv, kpe);

    // 6) causal flash attention (epilogue writes bf16x3 into A3)
    size_t attn_smem = (size_t)ATTN_SMEM_FLOATS * sizeof(float);
    cudaFuncSetAttribute(attn_kernel, cudaFuncAttributeMaxDynamicSharedMemorySize,
                         (int)attn_smem);
    dim3 agrid(S_LEN / 64, NHEAD);
    attn_kernel<<<agrid, 256, attn_smem>>>(qbuf, kvu, kpe, A3);

    // 7) output projection
    launch_split(wo, B3, DIM, NHEAD * VH, 1);
    launch_gemm3(A3, B3, out, S_LEN, DIM, NHEAD * VH);
}